// round 2
// baseline (speedup 1.0000x reference)
#include <cuda_runtime.h>

#define BATCH 64
#define CIN   96
#define CHID  256
#define COUT  80
#define TLEN  2048

// ---- scratch (allocation-free rule: __device__ globals) ----
static __device__ float    g_z1[(size_t)BATCH * TLEN * CHID];          // 128 MiB
static __device__ float    g_z2[(size_t)BATCH * TLEN * COUT];          // 40 MiB
static __device__ unsigned g_s1bits[(size_t)BATCH * TLEN * (CHID/32)]; // 4 MiB

// =====================================================================
// K1: layer-1 sparse GEMM.  z1[b][t][o] = sum_{i: x[b][i][t]!=0} W1[o][i]
// CTA = (t-chunk of 64, b). 256 threads (one per hidden neuron).
// W1 transposed into smem with stride 257 (conflict-free store AND load).
// Per-step 96-bit input masks built once per tile; inner loop walks set
// bits with __ffs in ascending i order (bit-exact vs sequential fp32
// ascending-k accumulation, since x is binary: adding 0.0 is exact).
// =====================================================================
__global__ __launch_bounds__(256) void k1_gemm1(const float* __restrict__ x,
                                                const float* __restrict__ W1) {
    extern __shared__ char smem_raw[];
    float*    w1t   = (float*)smem_raw;                  // [96][257]
    float*    xs    = w1t + CIN * 257;                   // [96][64]
    unsigned* masks = (unsigned*)(xs + CIN * 64);        // [64][3]

    const int tid = threadIdx.x;
    const int t0  = blockIdx.x * 64;
    const int b   = blockIdx.y;

    // load W1 [CHID][CIN] row-major, scatter to w1t[i*257+o]
    for (int idx = tid; idx < CHID * CIN; idx += 256) {
        int o = idx / CIN, i = idx % CIN;
        w1t[i * 257 + o] = W1[idx];
    }
    // load x tile [96][64] (coalesced: 64 contiguous t per row)
    const float* xb = x + (size_t)b * CIN * TLEN + t0;
    for (int idx = tid; idx < CIN * 64; idx += 256) {
        xs[idx] = xb[(size_t)(idx >> 6) * TLEN + (idx & 63)];
    }
    __syncthreads();

    // build per-step activity masks: thread = (tt, word)
    if (tid < 64 * 3) {
        int tt = tid / 3, w = tid % 3;
        unsigned m = 0;
        #pragma unroll
        for (int k = 0; k < 32; k++)
            if (xs[(w * 32 + k) * 64 + tt] != 0.0f) m |= (1u << k);
        masks[tt * 3 + w] = m;
    }
    __syncthreads();

    const int o = tid;
    float* zp = g_z1 + ((size_t)b * TLEN + t0) * CHID + o;
    for (int tt = 0; tt < 64; tt++) {
        float acc = 0.0f;
        #pragma unroll
        for (int w = 0; w < 3; w++) {
            unsigned m = masks[tt * 3 + w];
            const float* wp = w1t + (w * 32) * 257 + o;
            while (m) {
                int k = __ffs(m) - 1;
                m &= m - 1;
                acc += wp[k * 257];
            }
        }
        zp[(size_t)tt * CHID] = acc;   // 1KB coalesced store per step
    }
}

// =====================================================================
// LIF step helpers.  Matches the XLA-contracted reference:
//   v = fma(v, 0.95f, z)    (ONE rounding — XLA fuses mul+add)
//   s = (v >= 1.0f); v = s ? 0 : v
// =====================================================================
template <int U>
__device__ __forceinline__ void lif_proc_bits(float& v, const float (&zr)[U],
                                              int tbase, float* __restrict__ so,
                                              unsigned* __restrict__ bp, int lane) {
    #pragma unroll
    for (int u8 = 0; u8 < U; u8 += 8) {
        float sv[8];
        #pragma unroll
        for (int u = 0; u < 8; u++) {
            v = __fmaf_rn(v, 0.95f, zr[u8 + u]);
            bool sp = (v >= 1.0f);
            sv[u] = sp ? 1.0f : 0.0f;
            unsigned bal = __ballot_sync(0xffffffffu, sp);
            if (lane == 0) bp[(size_t)(tbase + u8 + u) * (CHID/32)] = bal;
            v = sp ? 0.0f : v;
        }
        *(float4*)(so + tbase + u8)     = make_float4(sv[0], sv[1], sv[2], sv[3]);
        *(float4*)(so + tbase + u8 + 4) = make_float4(sv[4], sv[5], sv[6], sv[7]);
    }
}

template <int U>
__device__ __forceinline__ void lif_proc(float& v, const float (&zr)[U],
                                         int tbase, float* __restrict__ so) {
    #pragma unroll
    for (int u8 = 0; u8 < U; u8 += 8) {
        float sv[8];
        #pragma unroll
        for (int u = 0; u < 8; u++) {
            v = __fmaf_rn(v, 0.95f, zr[u8 + u]);
            bool sp = (v >= 1.0f);
            sv[u] = sp ? 1.0f : 0.0f;
            v = sp ? 0.0f : v;
        }
        *(float4*)(so + tbase + u8)     = make_float4(sv[0], sv[1], sv[2], sv[3]);
        *(float4*)(so + tbase + u8 + 4) = make_float4(sv[4], sv[5], sv[6], sv[7]);
    }
}

// =====================================================================
// K2: layer-1 LIF scan. 16384 threads = (b, o). Reads z1[b][t][o]
// (warp-coalesced 128B per step), writes spikes to d_out[b][o][t]
// (32B/thread buffered stores) + ballot-packed bits for K3.
// Depth-2 register prefetch (U=32 steps) hides DRAM latency behind
// the dependent v-chain.
// =====================================================================
__global__ __launch_bounds__(128) void k2_scan1(float* __restrict__ out) {
    const int gid  = blockIdx.x * 128 + threadIdx.x;   // 0..16383
    const int b    = gid >> 8;
    const int o    = gid & 255;
    const int lane = o & 31;
    const float* z  = g_z1 + (size_t)b * TLEN * CHID + o;
    float*       so = out + ((size_t)b * CHID + o) * TLEN;
    unsigned*    bp = g_s1bits + (size_t)b * TLEN * (CHID/32) + (o >> 5);

    constexpr int U = 32;
    float za[U], zb[U];
    float v = 0.0f;
    #pragma unroll
    for (int u = 0; u < U; u++) za[u] = __ldg(&z[(size_t)u * CHID]);

    for (int t = 0; t < TLEN; t += 2 * U) {
        #pragma unroll
        for (int u = 0; u < U; u++) zb[u] = __ldg(&z[(size_t)(t + U + u) * CHID]);
        lif_proc_bits<U>(v, za, t, so, bp, lane);
        if (t + 2 * U < TLEN) {
            #pragma unroll
            for (int u = 0; u < U; u++) za[u] = __ldg(&z[(size_t)(t + 2*U + u) * CHID]);
        }
        lif_proc_bits<U>(v, zb, t + U, so, bp, lane);
    }
}

// =====================================================================
// K3: layer-2 sparse GEMM from packed spike bits.
// CTA = (t-chunk of 128, b). 384 threads = 4 groups of 96 (3 warps each,
// so the per-step mask is warp-uniform -> no divergence). j = r (<80).
// W2 transposed into smem with stride 81 (conflict-free).
// =====================================================================
__global__ __launch_bounds__(384) void k3_gemm2(const float* __restrict__ W2) {
    extern __shared__ char smem_raw[];
    float*    w2t = (float*)smem_raw;              // [256][81]
    unsigned* mb  = (unsigned*)(w2t + CHID * 81);  // [128][8]

    const int tid = threadIdx.x;
    const int t0  = blockIdx.x * 128;
    const int b   = blockIdx.y;

    for (int idx = tid; idx < COUT * CHID; idx += 384) {
        int j = idx / CHID, o = idx % CHID;
        w2t[o * 81 + j] = W2[idx];
    }
    const unsigned* sb = g_s1bits + ((size_t)b * TLEN + t0) * (CHID/32);
    for (int idx = tid; idx < 128 * (CHID/32); idx += 384) mb[idx] = sb[idx];
    __syncthreads();

    const int grp = tid / 96;            // 0..3 (3 full warps each)
    const int r   = tid % 96;
    const int j   = (r < COUT) ? r : (COUT - 1);  // idle lanes shadow j=79
    float* zo = g_z2 + ((size_t)b * TLEN + t0) * COUT;

    for (int tt = grp; tt < 128; tt += 4) {
        float acc = 0.0f;
        #pragma unroll
        for (int w = 0; w < CHID/32; w++) {
            unsigned m = mb[tt * (CHID/32) + w];
            const float* wp = w2t + (w * 32) * 81 + j;
            while (m) {
                int k = __ffs(m) - 1;
                m &= m - 1;
                acc += wp[k * 81];
            }
        }
        if (r < COUT) zo[(size_t)tt * COUT + j] = acc;  // 320B coalesced
    }
}

// =====================================================================
// K4: layer-2 LIF scan. 5120 threads = (b, j).
// =====================================================================
__global__ __launch_bounds__(128) void k4_scan2(float* __restrict__ out) {
    const int gid = blockIdx.x * 128 + threadIdx.x;   // 0..5119
    const int b = gid / COUT;
    const int j = gid % COUT;
    const float* z  = g_z2 + (size_t)b * TLEN * COUT + j;
    float*       so = out + (size_t)BATCH * CHID * TLEN
                          + ((size_t)b * COUT + j) * TLEN;

    constexpr int U = 32;
    float za[U], zb[U];
    float v = 0.0f;
    #pragma unroll
    for (int u = 0; u < U; u++) za[u] = __ldg(&z[(size_t)u * COUT]);

    for (int t = 0; t < TLEN; t += 2 * U) {
        #pragma unroll
        for (int u = 0; u < U; u++) zb[u] = __ldg(&z[(size_t)(t + U + u) * COUT]);
        lif_proc<U>(v, za, t, so);
        if (t + 2 * U < TLEN) {
            #pragma unroll
            for (int u = 0; u < U; u++) za[u] = __ldg(&z[(size_t)(t + 2*U + u) * COUT]);
        }
        lif_proc<U>(v, zb, t + U, so);
    }
}

// =====================================================================
extern "C" void kernel_launch(void* const* d_in, const int* in_sizes, int n_in,
                              void* d_out, int out_size) {
    const float* x  = (const float*)d_in[0];   // [64, 96, 2048]
    const float* W1 = (const float*)d_in[1];   // [256, 96]
    const float* W2 = (const float*)d_in[2];   // [80, 256]
    float* out = (float*)d_out;                // spk1 (64*256*2048) ++ spk2 (64*80*2048)

    const int smem1 = (CIN * 257 + CIN * 64) * 4 + 64 * 3 * 4;      // ~124 KB
    const int smem3 = (CHID * 81) * 4 + 128 * (CHID/32) * 4;        // ~87 KB
    cudaFuncSetAttribute(k1_gemm1, cudaFuncAttributeMaxDynamicSharedMemorySize, smem1);
    cudaFuncSetAttribute(k3_gemm2, cudaFuncAttributeMaxDynamicSharedMemorySize, smem3);

    k1_gemm1<<<dim3(TLEN / 64, BATCH), 256, smem1>>>(x, W1);
    k2_scan1<<<(BATCH * CHID) / 128, 128>>>(out);
    k3_gemm2<<<dim3(TLEN / 128, BATCH), 384, smem3>>>(W2);
    k4_scan2<<<(BATCH * COUT) / 128, 128>>>(out);
}

// round 3
// speedup vs baseline: 2.3612x; 2.3612x over previous
#include <cuda_runtime.h>

#define BATCH 64
#define CIN   96
#define CHID  256
#define COUT  80
#define TLEN  2048

// ---- scratch (allocation-free rule: __device__ globals) ----
static __device__ float    g_z1[(size_t)BATCH * TLEN * CHID];          // 128 MiB
static __device__ float    g_z2[(size_t)BATCH * TLEN * COUT];          // 40 MiB
static __device__ unsigned g_s1bits[(size_t)BATCH * TLEN * (CHID/32)]; // 4 MiB

// =====================================================================
// K1: layer-1 sparse GEMM via zero-padded index lists.
//   z1[b][t][o] = sum_{i active} W1[o][i]   (ascending i, bit-exact)
// CTA = (t-chunk 128, b), 256 threads. Each thread: 2 adjacent o via
// LDS.64 (stride 258 even -> aligned, conflict-free), half the steps.
// Lists hold i*258 (uint16), padded to x8 with dummy row 96 (zeros).
// =====================================================================
__global__ __launch_bounds__(256) void k1_gemm1(const float* __restrict__ x,
                                                const float* __restrict__ W1) {
    extern __shared__ char sm[];
    float*          w1t    = (float*)sm;                          // [97][258] (+pad)
    unsigned short* lists  = (unsigned short*)(sm + 100112);      // [64][104]
    int*            counts = (int*)(sm + 113424);                 // [64]
    float*          xs     = (float*)(sm + 113680);               // [96][64]

    const int tid = threadIdx.x;
    const int t0  = blockIdx.x * 128;
    const int b   = blockIdx.y;

    // W1 [256][96] -> w1t[i*258 + o]; zero dummy row i=96
    for (int idx = tid; idx < CHID * CIN; idx += 256) {
        int o = idx / CIN, i = idx % CIN;
        w1t[i * 258 + o] = W1[idx];
    }
    for (int idx = tid; idx < 258; idx += 256) w1t[96 * 258 + idx] = 0.0f;

    const int o    = 2 * (tid & 127);
    const int half = tid >> 7;

    for (int sub = 0; sub < 2; sub++) {
        __syncthreads();  // w1t ready (sub 0) / xs reuse safe (sub 1)
        const float* xb = x + (size_t)b * CIN * TLEN + t0 + sub * 64;
        for (int idx = tid; idx < CIN * 64; idx += 256) {
            int i = idx >> 6, tt = idx & 63;
            xs[idx] = xb[(size_t)i * TLEN + tt];
        }
        __syncthreads();
        if (tid < 64) {  // build ascending index list for step tid
            int tt = tid, c = 0;
            unsigned short* L = lists + tt * 104;
            for (int i = 0; i < CIN; i++)
                if (xs[i * 64 + tt] != 0.0f) L[c++] = (unsigned short)(i * 258);
            while (c & 7) L[c++] = (unsigned short)(96 * 258);
            counts[tt] = c;
        }
        __syncthreads();

        float* zp = g_z1 + ((size_t)b * TLEN + t0 + sub * 64) * CHID + o;
        for (int tt = half; tt < 64; tt += 2) {
            const int cnt = counts[tt];
            const unsigned short* L = lists + tt * 104;
            float a0 = 0.0f, a1 = 0.0f;
            for (int p = 0; p < cnt; p += 8) {
                uint4 lw = *(const uint4*)(L + p);
                int e0 = lw.x & 0xffff, e1 = lw.x >> 16;
                int e2 = lw.y & 0xffff, e3 = lw.y >> 16;
                int e4 = lw.z & 0xffff, e5 = lw.z >> 16;
                int e6 = lw.w & 0xffff, e7 = lw.w >> 16;
                float2 w;
                w = *(const float2*)(w1t + e0 + o); a0 += w.x; a1 += w.y;
                w = *(const float2*)(w1t + e1 + o); a0 += w.x; a1 += w.y;
                w = *(const float2*)(w1t + e2 + o); a0 += w.x; a1 += w.y;
                w = *(const float2*)(w1t + e3 + o); a0 += w.x; a1 += w.y;
                w = *(const float2*)(w1t + e4 + o); a0 += w.x; a1 += w.y;
                w = *(const float2*)(w1t + e5 + o); a0 += w.x; a1 += w.y;
                w = *(const float2*)(w1t + e6 + o); a0 += w.x; a1 += w.y;
                w = *(const float2*)(w1t + e7 + o); a0 += w.x; a1 += w.y;
            }
            *(float2*)(zp + (size_t)tt * CHID) = make_float2(a0, a1);
        }
    }
}

// =====================================================================
// LIF batch processors.  v = fma(v, 0.95f, z) — matches XLA contraction.
// =====================================================================
__device__ __forceinline__ void proc32_bits(float& v, const float (&z)[32],
                                            int tbase, float* __restrict__ so,
                                            unsigned* __restrict__ bw, int lane) {
    unsigned keep = 0;
    #pragma unroll
    for (int u8 = 0; u8 < 32; u8 += 8) {
        float sv[8];
        #pragma unroll
        for (int u = 0; u < 8; u++) {
            const int st = u8 + u;
            v = __fmaf_rn(v, 0.95f, z[st]);
            bool sp = (v >= 1.0f);
            sv[u] = sp ? 1.0f : 0.0f;
            unsigned bal = __ballot_sync(0xffffffffu, sp);
            keep = (lane == st) ? bal : keep;
            v = sp ? 0.0f : v;
        }
        *(float4*)(so + tbase + u8)     = make_float4(sv[0], sv[1], sv[2], sv[3]);
        *(float4*)(so + tbase + u8 + 4) = make_float4(sv[4], sv[5], sv[6], sv[7]);
    }
    bw[(size_t)(tbase + lane) * (CHID/32)] = keep;  // one scattered STG per 32 steps
}

__device__ __forceinline__ void proc32(float& v, const float (&z)[32],
                                       int tbase, float* __restrict__ so) {
    #pragma unroll
    for (int u8 = 0; u8 < 32; u8 += 8) {
        float sv[8];
        #pragma unroll
        for (int u = 0; u < 8; u++) {
            v = __fmaf_rn(v, 0.95f, z[u8 + u]);
            bool sp = (v >= 1.0f);
            sv[u] = sp ? 1.0f : 0.0f;
            v = sp ? 0.0f : v;
        }
        *(float4*)(so + tbase + u8)     = make_float4(sv[0], sv[1], sv[2], sv[3]);
        *(float4*)(so + tbase + u8 + 4) = make_float4(sv[4], sv[5], sv[6], sv[7]);
    }
}

// =====================================================================
// K2: layer-1 LIF scan. block=64 -> 256 CTAs spread over all SMs.
// 4 rotating 32-step register buffers (prefetch distance 3 ~= 1150cyc).
// =====================================================================
#define LD32(dst, zp, t) { _Pragma("unroll") \
    for (int u = 0; u < 32; u++) dst[u] = __ldg(zp + (size_t)((t) + u) * CHID); }

__global__ __launch_bounds__(64) void k2_scan1(float* __restrict__ out) {
    const int gid  = blockIdx.x * 64 + threadIdx.x;   // 0..16383
    const int b    = gid >> 8;
    const int o    = gid & 255;
    const int lane = o & 31;
    const float* z  = g_z1 + (size_t)b * TLEN * CHID + o;
    float*       so = out + ((size_t)b * CHID + o) * TLEN;
    unsigned*    bw = g_s1bits + (size_t)b * TLEN * (CHID/32) + (o >> 5);

    float A[32], B[32], C[32], D[32];
    float v = 0.0f;
    LD32(A, z, 0); LD32(B, z, 32); LD32(C, z, 64);

    for (int bi = 0; bi < 64; bi += 4) {
        const int t = bi * 32;
        if (bi + 3 < 64) LD32(D, z, t + 96);
        proc32_bits(v, A, t, so, bw, lane);
        if (bi + 4 < 64) LD32(A, z, t + 128);
        proc32_bits(v, B, t + 32, so, bw, lane);
        if (bi + 5 < 64) LD32(B, z, t + 160);
        proc32_bits(v, C, t + 64, so, bw, lane);
        if (bi + 6 < 64) LD32(C, z, t + 192);
        proc32_bits(v, D, t + 96, so, bw, lane);
    }
}

// =====================================================================
// K3: layer-2 sparse GEMM from packed spike bits via index lists.
// CTA = (t-chunk 64, b), 384 threads = 4 groups x 96 (3 warps each).
// Lists hold o*81 (uint16), padded x8 with dummy row 256 (zeros).
// =====================================================================
__global__ __launch_bounds__(384) void k3_gemm2(const float* __restrict__ W2) {
    extern __shared__ char sm[];
    float*          w2t    = (float*)sm;                      // [257][81] (+pad)
    unsigned short* lists  = (unsigned short*)(sm + 83280);   // [64][264]
    int*            counts = (int*)(sm + 117072);             // [64]

    const int tid = threadIdx.x;
    const int t0  = blockIdx.x * 64;
    const int b   = blockIdx.y;

    // W2 [80][256] -> w2t[o*81 + j]; (o*81+j) mod 32 = (o*17+j): conflict-free
    for (int idx = tid; idx < COUT * CHID; idx += 384) {
        int j = idx / CHID, o = idx % CHID;
        w2t[o * 81 + j] = W2[idx];
    }
    for (int idx = tid; idx < 81; idx += 384) w2t[256 * 81 + idx] = 0.0f;

    if (tid < 64) {  // build ascending o-list for step tid
        const int tt = tid;
        const unsigned* sb = g_s1bits + ((size_t)b * TLEN + t0 + tt) * (CHID/32);
        unsigned short* L = lists + tt * 264;
        int c = 0;
        #pragma unroll
        for (int w = 0; w < CHID/32; w++) {
            unsigned m = sb[w];
            while (m) {
                int k = __ffs(m) - 1;
                m &= m - 1;
                L[c++] = (unsigned short)((w * 32 + k) * 81);
            }
        }
        while (c & 7) L[c++] = (unsigned short)(256 * 81);
        counts[tt] = c;
    }
    __syncthreads();

    const int grp = tid / 96;            // 0..3 (3 full warps each)
    const int r   = tid % 96;
    float* zo = g_z2 + ((size_t)b * TLEN + t0) * COUT;

    if (r < COUT) {
        const int j = r;
        for (int tt = grp; tt < 64; tt += 4) {
            const int cnt = counts[tt];
            const unsigned short* L = lists + tt * 264;
            float acc = 0.0f;
            for (int p = 0; p < cnt; p += 8) {
                uint4 lw = *(const uint4*)(L + p);
                acc += w2t[(lw.x & 0xffff) + j];
                acc += w2t[(lw.x >> 16)    + j];
                acc += w2t[(lw.y & 0xffff) + j];
                acc += w2t[(lw.y >> 16)    + j];
                acc += w2t[(lw.z & 0xffff) + j];
                acc += w2t[(lw.z >> 16)    + j];
                acc += w2t[(lw.w & 0xffff) + j];
                acc += w2t[(lw.w >> 16)    + j];
            }
            zo[(size_t)tt * COUT + j] = acc;
        }
    }
}

// =====================================================================
// K4: layer-2 LIF scan. block=32 -> 160 CTAs (all SMs engaged),
// same 4-buffer prefetch.
// =====================================================================
#define LD32B(dst, zp, t) { _Pragma("unroll") \
    for (int u = 0; u < 32; u++) dst[u] = __ldg(zp + (size_t)((t) + u) * COUT); }

__global__ __launch_bounds__(32) void k4_scan2(float* __restrict__ out) {
    const int gid = blockIdx.x * 32 + threadIdx.x;   // 0..5119
    const int b = gid / COUT;
    const int j = gid % COUT;
    const float* z  = g_z2 + (size_t)b * TLEN * COUT + j;
    float*       so = out + (size_t)BATCH * CHID * TLEN
                          + ((size_t)b * COUT + j) * TLEN;

    float A[32], B[32], C[32], D[32];
    float v = 0.0f;
    LD32B(A, z, 0); LD32B(B, z, 32); LD32B(C, z, 64);

    for (int bi = 0; bi < 64; bi += 4) {
        const int t = bi * 32;
        if (bi + 3 < 64) LD32B(D, z, t + 96);
        proc32(v, A, t, so);
        if (bi + 4 < 64) LD32B(A, z, t + 128);
        proc32(v, B, t + 32, so);
        if (bi + 5 < 64) LD32B(B, z, t + 160);
        proc32(v, C, t + 64, so);
        if (bi + 6 < 64) LD32B(C, z, t + 192);
        proc32(v, D, t + 96, so);
    }
}

// =====================================================================
extern "C" void kernel_launch(void* const* d_in, const int* in_sizes, int n_in,
                              void* d_out, int out_size) {
    const float* x  = (const float*)d_in[0];   // [64, 96, 2048]
    const float* W1 = (const float*)d_in[1];   // [256, 96]
    const float* W2 = (const float*)d_in[2];   // [80, 256]
    float* out = (float*)d_out;                // spk1 ++ spk2

    const int smem1 = 138256;   // w1t 100112 + lists 13312 + counts 256 + xs 24576
    const int smem3 = 117328;   // w2t 83280 + lists 33792 + counts 256
    cudaFuncSetAttribute(k1_gemm1, cudaFuncAttributeMaxDynamicSharedMemorySize, smem1);
    cudaFuncSetAttribute(k3_gemm2, cudaFuncAttributeMaxDynamicSharedMemorySize, smem3);

    k1_gemm1<<<dim3(TLEN / 128, BATCH), 256, smem1>>>(x, W1);
    k2_scan1<<<(BATCH * CHID) / 64, 64>>>(out);
    k3_gemm2<<<dim3(TLEN / 64, BATCH), 384, smem3>>>(W2);
    k4_scan2<<<(BATCH * COUT) / 32, 32>>>(out);
}